// round 5
// baseline (speedup 1.0000x reference)
#include <cuda_runtime.h>
#include <cuda_bf16.h>
#include <math.h>

#define D_MODEL   1024
#define NUM_HEADS 16
#define HEAD_DIM  64
#define BATCH     2
#define SEQ       2048
#define NROWS     (BATCH * SEQ)   // 4096

// ---------------------------------------------------------------------------
// Scratch (device globals; no runtime allocation allowed)
// ---------------------------------------------------------------------------
__device__ float g_Q [(size_t)NROWS * D_MODEL];
__device__ float g_K [(size_t)NROWS * D_MODEL];
__device__ float g_V [(size_t)NROWS * D_MODEL];
__device__ float g_AO[(size_t)NROWS * D_MODEL];

__device__ __forceinline__ float* scratch_ptr(int sel) {
    switch (sel) {
        case 0: return g_Q;
        case 1: return g_K;
        case 2: return g_V;
        default: return g_AO;
    }
}

// ---------------------------------------------------------------------------
// SGEMM: C[M,N] = A[M,K] @ W[K,N] + bias[N]
// 128x128 block tile, BK=8, 256 threads, 8x8 microtile per thread.
// aSel/cSel >= 0 redirect A/C to a device scratch buffer (avoids
// cudaGetSymbolAddress on the host path).
// M,N,K assumed multiples of 128/8 (true here: 4096/1024/1024).
// ---------------------------------------------------------------------------
__global__ __launch_bounds__(256)
void sgemm_bias_kernel(const float* A, int aSel,
                       const float* W,
                       const float* bias,
                       float* C, int cSel,
                       int M, int N, int K)
{
    if (aSel >= 0) A = scratch_ptr(aSel);
    if (cSel >= 0) C = scratch_ptr(cSel);

    __shared__ float As[8][128];   // [k][m] (transposed)
    __shared__ float Bs[8][128];   // [k][n]

    const int tid = threadIdx.x;
    const int tx  = tid & 15;      // 0..15 -> N microtile
    const int ty  = tid >> 4;      // 0..15 -> M microtile

    const int rowBase = blockIdx.y * 128;
    const int colBase = blockIdx.x * 128;

    // A loader: 128 rows x 8 cols, one float4 per thread
    const int aRow = tid >> 1;           // 0..127
    const int aCol = (tid & 1) * 4;      // 0 or 4
    // W loader: 8 rows x 128 cols, one float4 per thread
    const int bRow = tid >> 5;           // 0..7
    const int bCol = (tid & 31) * 4;     // 0..124

    const float* Aptr = A + (size_t)(rowBase + aRow) * K + aCol;
    const float* Wptr = W + (size_t)bRow * N + colBase + bCol;

    float acc[8][8];
#pragma unroll
    for (int i = 0; i < 8; i++)
#pragma unroll
        for (int j = 0; j < 8; j++) acc[i][j] = 0.f;

    for (int k0 = 0; k0 < K; k0 += 8) {
        float4 av = *(const float4*)(Aptr + k0);
        float4 bv = *(const float4*)(Wptr + (size_t)k0 * N);

        __syncthreads();   // previous iteration's compute must finish
        As[aCol + 0][aRow] = av.x;
        As[aCol + 1][aRow] = av.y;
        As[aCol + 2][aRow] = av.z;
        As[aCol + 3][aRow] = av.w;
        *(float4*)&Bs[bRow][bCol] = bv;
        __syncthreads();

#pragma unroll
        for (int kk = 0; kk < 8; kk++) {
            float4 a0 = *(const float4*)&As[kk][ty * 4];
            float4 a1 = *(const float4*)&As[kk][64 + ty * 4];
            float4 b0 = *(const float4*)&Bs[kk][tx * 4];
            float4 b1 = *(const float4*)&Bs[kk][64 + tx * 4];
            float ar[8] = {a0.x, a0.y, a0.z, a0.w, a1.x, a1.y, a1.z, a1.w};
            float br[8] = {b0.x, b0.y, b0.z, b0.w, b1.x, b1.y, b1.z, b1.w};
#pragma unroll
            for (int i = 0; i < 8; i++)
#pragma unroll
                for (int j = 0; j < 8; j++)
                    acc[i][j] = fmaf(ar[i], br[j], acc[i][j]);
        }
    }

    float4 bs0 = *(const float4*)&bias[colBase + tx * 4];
    float4 bs1 = *(const float4*)&bias[colBase + 64 + tx * 4];
    const float bb0[4] = {bs0.x, bs0.y, bs0.z, bs0.w};
    const float bb1[4] = {bs1.x, bs1.y, bs1.z, bs1.w};

#pragma unroll
    for (int i = 0; i < 8; i++) {
        int r = rowBase + ((i < 4) ? (ty * 4 + i) : (64 + ty * 4 + (i - 4)));
        float4 v0, v1;
        v0.x = acc[i][0] + bb0[0]; v0.y = acc[i][1] + bb0[1];
        v0.z = acc[i][2] + bb0[2]; v0.w = acc[i][3] + bb0[3];
        v1.x = acc[i][4] + bb1[0]; v1.y = acc[i][5] + bb1[1];
        v1.z = acc[i][6] + bb1[2]; v1.w = acc[i][7] + bb1[3];
        *(float4*)&C[(size_t)r * N + colBase + tx * 4]      = v0;
        *(float4*)&C[(size_t)r * N + colBase + 64 + tx * 4] = v1;
    }
}

// ---------------------------------------------------------------------------
// Attention per (b, h, 64-row Q tile). 256 threads, 4x4 microtile each.
// Pass 1: raw scores -> attnW (scratch region == final output region),
//         exact online (m, l) per row via width-16 shuffle butterflies.
// Pass 2: re-read raw scores (same thread wrote them), emit final softmax
//         weights, accumulate P @ V into g_AO.
// SMEM buffers reused: smA = Q^T (pass1) / P^T (pass2),
//                      smB = K^T (pass1) / V   (pass2).
// ---------------------------------------------------------------------------
__global__ __launch_bounds__(256)
void attn_kernel(const int* __restrict__ mask, float* __restrict__ attnW)
{
    const int qt  = blockIdx.x;     // 0..31
    const int h   = blockIdx.y;     // 0..15
    const int b   = blockIdx.z;     // 0..1
    const int tid = threadIdx.x;
    const int tx  = tid & 15;       // key/value-dim microtile
    const int ty  = tid >> 4;       // query-row microtile

    __shared__ float smA[64][68];   // pass1: Q^T[d][q]; pass2: P^T[k][q]
    __shared__ float smB[64][68];   // pass1: K^T[d][k]; pass2: V[k][d]
    __shared__ int   maskS[64];

    const int q0   = qt * 64;
    const int ldr  = tid >> 4;          // 0..15
    const int ldc4 = (tid & 15) * 4;    // 0..60

    // Load Q tile transposed: smA[d][q]
#pragma unroll
    for (int i = 0; i < 4; i++) {
        int q = ldr + i * 16;
        float4 v = *(const float4*)&g_Q[(size_t)(b * SEQ + q0 + q) * D_MODEL
                                        + h * HEAD_DIM + ldc4];
        smA[ldc4 + 0][q] = v.x; smA[ldc4 + 1][q] = v.y;
        smA[ldc4 + 2][q] = v.z; smA[ldc4 + 3][q] = v.w;
    }

    float m[4], l[4];
#pragma unroll
    for (int i = 0; i < 4; i++) { m[i] = -3.0e38f; l[i] = 0.f; }

    const size_t attnRowBase = (size_t)(b * NUM_HEADS + h) * SEQ + q0;

    // ---------------- Pass 1: scores + online softmax stats ----------------
    for (int ks = 0; ks < SEQ; ks += 64) {
        __syncthreads();
#pragma unroll
        for (int i = 0; i < 4; i++) {
            int k = ldr + i * 16;
            float4 v = *(const float4*)&g_K[(size_t)(b * SEQ + ks + k) * D_MODEL
                                            + h * HEAD_DIM + ldc4];
            smB[ldc4 + 0][k] = v.x; smB[ldc4 + 1][k] = v.y;
            smB[ldc4 + 2][k] = v.z; smB[ldc4 + 3][k] = v.w;
        }
        if (tid < 64) maskS[tid] = mask[b * SEQ + ks + tid];
        __syncthreads();

        float s[4][4];
#pragma unroll
        for (int i = 0; i < 4; i++)
#pragma unroll
            for (int j = 0; j < 4; j++) s[i][j] = 0.f;

#pragma unroll 8
        for (int kk = 0; kk < 64; kk++) {
            float4 a  = *(const float4*)&smA[kk][ty * 4];
            float4 bb = *(const float4*)&smB[kk][tx * 4];
            float ar[4] = {a.x, a.y, a.z, a.w};
            float br[4] = {bb.x, bb.y, bb.z, bb.w};
#pragma unroll
            for (int i = 0; i < 4; i++)
#pragma unroll
                for (int j = 0; j < 4; j++)
                    s[i][j] = fmaf(ar[i], br[j], s[i][j]);
        }

        // scale 1/sqrt(64), apply mask
#pragma unroll
        for (int j = 0; j < 4; j++) {
            bool masked = (maskS[tx * 4 + j] == 0);
#pragma unroll
            for (int i = 0; i < 4; i++) {
                float sv = s[i][j] * 0.125f;
                s[i][j] = masked ? -3.0e38f : sv;
            }
        }

        // write raw scores (scratch in the output region; overwritten pass 2)
#pragma unroll
        for (int i = 0; i < 4; i++) {
            size_t idx = (attnRowBase + ty * 4 + i) * SEQ + ks + tx * 4;
            *(float4*)&attnW[idx] = make_float4(s[i][0], s[i][1], s[i][2], s[i][3]);
        }

        // online (m, l) update; 16 lanes (same ty) share each row group
#pragma unroll
        for (int i = 0; i < 4; i++) {
            float tm = fmaxf(fmaxf(s[i][0], s[i][1]), fmaxf(s[i][2], s[i][3]));
#pragma unroll
            for (int off = 8; off; off >>= 1)
                tm = fmaxf(tm, __shfl_xor_sync(0xffffffffu, tm, off, 16));
            float nm = fmaxf(m[i], tm);
            float ps = __expf(s[i][0] - nm) + __expf(s[i][1] - nm)
                     + __expf(s[i][2] - nm) + __expf(s[i][3] - nm);
#pragma unroll
            for (int off = 8; off; off >>= 1)
                ps += __shfl_xor_sync(0xffffffffu, ps, off, 16);
            l[i] = l[i] * __expf(m[i] - nm) + ps;
            m[i] = nm;
        }
    }

    float invl[4];
#pragma unroll
    for (int i = 0; i < 4; i++) invl[i] = 1.0f / l[i];

    float o[4][4];
#pragma unroll
    for (int i = 0; i < 4; i++)
#pragma unroll
        for (int j = 0; j < 4; j++) o[i][j] = 0.f;

    // ---------------- Pass 2: finalize P, accumulate P @ V ----------------
    for (int ks = 0; ks < SEQ; ks += 64) {
        __syncthreads();
#pragma unroll
        for (int i = 0; i < 4; i++) {
            int k = ldr + i * 16;
            float4 v = *(const float4*)&g_V[(size_t)(b * SEQ + ks + k) * D_MODEL
                                            + h * HEAD_DIM + ldc4];
            *(float4*)&smB[k][ldc4] = v;    // V[k][d]
        }
#pragma unroll
        for (int i = 0; i < 4; i++) {
            size_t idx = (attnRowBase + ty * 4 + i) * SEQ + ks + tx * 4;
            float4 sv = *(const float4*)&attnW[idx];   // same thread wrote these
            float4 p;
            p.x = __expf(sv.x - m[i]) * invl[i];
            p.y = __expf(sv.y - m[i]) * invl[i];
            p.z = __expf(sv.z - m[i]) * invl[i];
            p.w = __expf(sv.w - m[i]) * invl[i];
            *(float4*)&attnW[idx] = p;                 // final softmax weights
            smA[tx * 4 + 0][ty * 4 + i] = p.x;         // P^T[k][q]
            smA[tx * 4 + 1][ty * 4 + i] = p.y;
            smA[tx * 4 + 2][ty * 4 + i] = p.z;
            smA[tx * 4 + 3][ty * 4 + i] = p.w;
        }
        __syncthreads();

#pragma unroll 8
        for (int kk = 0; kk < 64; kk++) {
            float4 a  = *(const float4*)&smA[kk][ty * 4];   // P rows
            float4 bb = *(const float4*)&smB[kk][tx * 4];   // V cols
            float ar[4] = {a.x, a.y, a.z, a.w};
            float br[4] = {bb.x, bb.y, bb.z, bb.w};
#pragma unroll
            for (int i = 0; i < 4; i++)
#pragma unroll
                for (int j = 0; j < 4; j++)
                    o[i][j] = fmaf(ar[i], br[j], o[i][j]);
        }
    }

    // attn_out in [B,S,H*Dh] layout -> ready for the O projection GEMM
#pragma unroll
    for (int i = 0; i < 4; i++) {
        size_t idx = (size_t)(b * SEQ + q0 + ty * 4 + i) * D_MODEL
                   + h * HEAD_DIM + tx * 4;
        *(float4*)&g_AO[idx] = make_float4(o[i][0], o[i][1], o[i][2], o[i][3]);
    }
}

// ---------------------------------------------------------------------------
// Launch: QKV projections -> attention -> output projection.
// Output layout: [output (B,S,D)] ++ [attn_weights (B,H,S,S)], fp32.
// ---------------------------------------------------------------------------
extern "C" void kernel_launch(void* const* d_in, const int* in_sizes, int n_in,
                              void* d_out, int out_size)
{
    const float* x  = (const float*)d_in[0];
    const int*   am = (const int*)  d_in[1];
    const float* Wq = (const float*)d_in[2];
    const float* bq = (const float*)d_in[3];
    const float* Wk = (const float*)d_in[4];
    const float* bk = (const float*)d_in[5];
    const float* Wv = (const float*)d_in[6];
    const float* bv = (const float*)d_in[7];
    const float* Wo = (const float*)d_in[8];
    const float* bo = (const float*)d_in[9];

    float* out   = (float*)d_out;
    float* attnW = out + (size_t)NROWS * D_MODEL;

    dim3 gGemm(D_MODEL / 128, NROWS / 128);   // (8, 32)

    sgemm_bias_kernel<<<gGemm, 256>>>(x, -1, Wq, bq, nullptr, 0,
                                      NROWS, D_MODEL, D_MODEL);
    sgemm_bias_kernel<<<gGemm, 256>>>(x, -1, Wk, bk, nullptr, 1,
                                      NROWS, D_MODEL, D_MODEL);
    sgemm_bias_kernel<<<gGemm, 256>>>(x, -1, Wv, bv, nullptr, 2,
                                      NROWS, D_MODEL, D_MODEL);

    dim3 gAttn(SEQ / 64, NUM_HEADS, BATCH);   // (32, 16, 2)
    attn_kernel<<<gAttn, 256>>>(am, attnW);

    sgemm_bias_kernel<<<gGemm, 256>>>(nullptr, 3, Wo, bo, out, -1,
                                      NROWS, D_MODEL, D_MODEL);
}